// round 2
// baseline (speedup 1.0000x reference)
#include <cuda_runtime.h>
#include <cstdint>

// Chamfer distance: pred/gt are [4, 8192, 3] fp32. Output: scalar fp32.
// mean_n min_m ||p_n - g_m||^2  +  mean_m min_n ||p_n - g_m||^2
//
// Strategy: d(p,g) = |p|^2 + (|g|^2 - 2 p.g). Query coords pre-scaled by -2,
// database point stored in smem duplicated as {x,x},{y,y},{z,z},{g2,g2} so the
// inner loop is 2x LDS.128 (warp broadcast) + 3x fma.rn.f32x2 + 2x FMNMX for
// 2 query points per lane (64 pairs per warp per j).

#define BATCH   4
#define NPTS    8192
#define THREADS 256
#define QPT     2                    // query points per thread (packed f32x2)
#define QPB     (THREADS * QPT)      // 512 queries per block
#define ITILES  (NPTS / QPB)         // 16
#define JSPLIT  8
#define JCHUNK  (NPTS / JSPLIT)      // 1024 database points per block

// scratch: per-point running min as uint bits (monotone for non-negative floats)
__device__ unsigned int g_min[2][BATCH * NPTS];

__device__ __forceinline__ unsigned long long pack2(float a, float b) {
    unsigned long long r;
    asm("mov.b64 %0, {%1, %2};" : "=l"(r) : "f"(a), "f"(b));
    return r;
}

__global__ void cd_init_kernel() {
    int i = blockIdx.x * blockDim.x + threadIdx.x;
    if (i < 2 * BATCH * NPTS) {
        ((unsigned int*)g_min)[i] = 0x7F800000u;  // +inf
    }
}

__global__ __launch_bounds__(THREADS)
void cd_main_kernel(const float* __restrict__ pred, const float* __restrict__ gt) {
    // smem: JCHUNK points x 32 bytes (duplicated packed layout) = 32 KB
    __shared__ ulonglong2 sm[JCHUNK * 2];

    const int bb    = blockIdx.z;          // batch
    const int dir   = blockIdx.y;          // 0: pred->gt, 1: gt->pred
    const int itile = blockIdx.x / JSPLIT;
    const int jc    = blockIdx.x % JSPLIT;

    const float* q  = (dir == 0 ? pred : gt) + (size_t)bb * NPTS * 3;
    const float* db = (dir == 0 ? gt : pred) + (size_t)bb * NPTS * 3;

    const int tid = threadIdx.x;

    // ---- stage database chunk into smem, duplicated-packed, with |g|^2 ----
    const int jbase = jc * JCHUNK;
    #pragma unroll
    for (int p = tid; p < JCHUNK; p += THREADS) {
        const float* g = db + (size_t)(jbase + p) * 3;
        float x = g[0], y = g[1], z = g[2];
        float g2 = fmaf(x, x, fmaf(y, y, z * z));
        sm[p * 2 + 0] = make_ulonglong2(pack2(x, x), pack2(y, y));
        sm[p * 2 + 1] = make_ulonglong2(pack2(z, z), pack2(g2, g2));
    }

    // ---- load this thread's 2 query points, pre-scale by -2 ----
    const int qi = itile * QPB + tid * 2;
    const float* q0 = q + (size_t)qi * 3;
    float p0x = q0[0], p0y = q0[1], p0z = q0[2];
    float p1x = q0[3], p1y = q0[4], p1z = q0[5];
    unsigned long long ax = pack2(-2.0f * p0x, -2.0f * p1x);
    unsigned long long ay = pack2(-2.0f * p0y, -2.0f * p1y);
    unsigned long long az = pack2(-2.0f * p0z, -2.0f * p1z);
    float p2_0 = fmaf(p0x, p0x, fmaf(p0y, p0y, p0z * p0z));
    float p2_1 = fmaf(p1x, p1x, fmaf(p1y, p1y, p1z * p1z));

    __syncthreads();

    // ---- main loop: 64 pairs per warp per j ----
    float m0 = __int_as_float(0x7F800000);
    float m1 = __int_as_float(0x7F800000);

    #pragma unroll 8
    for (int p = 0; p < JCHUNK; p++) {
        ulonglong2 w0 = sm[p * 2 + 0];   // {x,x},{y,y}
        ulonglong2 w1 = sm[p * 2 + 1];   // {z,z},{g2,g2}
        unsigned long long t;
        asm("fma.rn.f32x2 %0, %1, %2, %3;" : "=l"(t) : "l"(az), "l"(w1.x), "l"(w1.y));
        asm("fma.rn.f32x2 %0, %1, %2, %0;" : "+l"(t) : "l"(ay), "l"(w0.y));
        asm("fma.rn.f32x2 %0, %1, %2, %0;" : "+l"(t) : "l"(ax), "l"(w0.x));
        float lo = __uint_as_float((unsigned int)t);
        float hi = __uint_as_float((unsigned int)(t >> 32));
        m0 = fminf(m0, lo);
        m1 = fminf(m1, hi);
    }

    // add |p|^2 back; clamp tiny negative rounding so uint ordering is valid
    m0 = fmaxf(m0 + p2_0, 0.0f);
    m1 = fmaxf(m1 + p2_1, 0.0f);

    unsigned int* dst = &g_min[dir][bb * NPTS + qi];
    atomicMin(dst + 0, __float_as_uint(m0));
    atomicMin(dst + 1, __float_as_uint(m1));
}

__global__ void cd_reduce_kernel(float* __restrict__ out) {
    // single block, 1024 threads: sum both min arrays, scale, write scalar
    __shared__ float warp_sums[32];
    const int tid = threadIdx.x;
    float s = 0.0f;
    for (int i = tid; i < BATCH * NPTS; i += 1024) {
        s += __uint_as_float(g_min[0][i]);
        s += __uint_as_float(g_min[1][i]);
    }
    // warp reduce
    #pragma unroll
    for (int off = 16; off > 0; off >>= 1)
        s += __shfl_down_sync(0xFFFFFFFFu, s, off);
    if ((tid & 31) == 0) warp_sums[tid >> 5] = s;
    __syncthreads();
    if (tid < 32) {
        float v = (tid < (1024 / 32)) ? warp_sums[tid] : 0.0f;
        #pragma unroll
        for (int off = 16; off > 0; off >>= 1)
            v += __shfl_down_sync(0xFFFFFFFFu, v, off);
        if (tid == 0)
            out[0] = v / (float)(BATCH * NPTS);  // mean_pred + mean_gt (same denom)
    }
}

extern "C" void kernel_launch(void* const* d_in, const int* in_sizes, int n_in,
                              void* d_out, int out_size) {
    const float* pred = (const float*)d_in[0];
    const float* gt   = (const float*)d_in[1];
    float* out        = (float*)d_out;

    cd_init_kernel<<<(2 * BATCH * NPTS + 1023) / 1024, 1024>>>();

    dim3 grid(ITILES * JSPLIT, 2, BATCH);   // 128 x 2 x 4 = 1024 blocks
    cd_main_kernel<<<grid, THREADS>>>(pred, gt);

    cd_reduce_kernel<<<1, 1024>>>(out);
}

// round 3
// speedup vs baseline: 1.3235x; 1.3235x over previous
#include <cuda_runtime.h>
#include <cstdint>

// Chamfer distance: pred/gt are [4, 8192, 3] fp32. Output: scalar fp32.
// d(p,g) = |p|^2 + (|g|^2 - 2 p.g). Query coords pre-scaled by -2 and packed
// as f32x2 pairs (4 queries per lane). Database point staged in smem
// duplicated as {x,x},{y,y},{z,z},{g2,g2}: per j, one warp does
// 2x LDS.128 + 6x fma.rn.f32x2 + 4x FMNMX for 128 pairs.

#define BATCH   4
#define NPTS    8192
#define THREADS 256
#define QPT     4                    // query points per thread (2x packed f32x2)
#define QPB     (THREADS * QPT)      // 1024 queries per block
#define ITILES  (NPTS / QPB)         // 8
#define JSPLIT  16
#define JCHUNK  (NPTS / JSPLIT)      // 512 database points per block

// scratch: per-point running min as uint bits (monotone for non-negative floats)
__device__ unsigned int g_min[2][BATCH * NPTS];

__device__ __forceinline__ unsigned long long pack2(float a, float b) {
    unsigned long long r;
    asm("mov.b64 %0, {%1, %2};" : "=l"(r) : "f"(a), "f"(b));
    return r;
}

__global__ void cd_init_kernel() {
    int i = blockIdx.x * blockDim.x + threadIdx.x;
    if (i < 2 * BATCH * NPTS) {
        ((unsigned int*)g_min)[i] = 0x7F800000u;  // +inf
    }
}

__global__ __launch_bounds__(THREADS)
void cd_main_kernel(const float* __restrict__ pred, const float* __restrict__ gt) {
    // smem: JCHUNK points x 32 bytes (duplicated packed layout) = 16 KB
    __shared__ ulonglong2 sm[JCHUNK * 2];

    const int bb    = blockIdx.z;          // batch
    const int dir   = blockIdx.y;          // 0: pred->gt, 1: gt->pred
    const int itile = blockIdx.x / JSPLIT;
    const int jc    = blockIdx.x % JSPLIT;

    const float* q  = (dir == 0 ? pred : gt) + (size_t)bb * NPTS * 3;
    const float* db = (dir == 0 ? gt : pred) + (size_t)bb * NPTS * 3;

    const int tid = threadIdx.x;

    // ---- stage database chunk into smem, duplicated-packed, with |g|^2 ----
    const int jbase = jc * JCHUNK;
    #pragma unroll
    for (int p = tid; p < JCHUNK; p += THREADS) {
        const float* g = db + (size_t)(jbase + p) * 3;
        float x = g[0], y = g[1], z = g[2];
        float g2 = fmaf(x, x, fmaf(y, y, z * z));
        sm[p * 2 + 0] = make_ulonglong2(pack2(x, x), pack2(y, y));
        sm[p * 2 + 1] = make_ulonglong2(pack2(z, z), pack2(g2, g2));
    }

    // ---- load this thread's 4 query points (3x float4), pre-scale by -2 ----
    const int qi = itile * QPB + tid * QPT;
    const float4* q4 = (const float4*)(q + (size_t)qi * 3);  // 48B, 16B-aligned
    float4 a = q4[0];   // p0x p0y p0z p1x
    float4 b = q4[1];   // p1y p1z p2x p2y
    float4 c = q4[2];   // p2z p3x p3y p3z

    unsigned long long ax01 = pack2(-2.0f * a.x, -2.0f * a.w);
    unsigned long long ay01 = pack2(-2.0f * a.y, -2.0f * b.x);
    unsigned long long az01 = pack2(-2.0f * a.z, -2.0f * b.y);
    unsigned long long ax23 = pack2(-2.0f * b.z, -2.0f * c.y);
    unsigned long long ay23 = pack2(-2.0f * b.w, -2.0f * c.z);
    unsigned long long az23 = pack2(-2.0f * c.x, -2.0f * c.w);

    float p2_0 = fmaf(a.x, a.x, fmaf(a.y, a.y, a.z * a.z));
    float p2_1 = fmaf(a.w, a.w, fmaf(b.x, b.x, b.y * b.y));
    float p2_2 = fmaf(b.z, b.z, fmaf(b.w, b.w, c.x * c.x));
    float p2_3 = fmaf(c.y, c.y, fmaf(c.z, c.z, c.w * c.w));

    __syncthreads();

    // ---- main loop: 128 pairs per warp per j ----
    float m0 = __int_as_float(0x7F800000);
    float m1 = __int_as_float(0x7F800000);
    float m2 = __int_as_float(0x7F800000);
    float m3 = __int_as_float(0x7F800000);

    #pragma unroll 4
    for (int p = 0; p < JCHUNK; p++) {
        ulonglong2 w0 = sm[p * 2 + 0];   // {x,x},{y,y}
        ulonglong2 w1 = sm[p * 2 + 1];   // {z,z},{g2,g2}
        unsigned long long t0, t1;
        asm("fma.rn.f32x2 %0, %1, %2, %3;" : "=l"(t0) : "l"(az01), "l"(w1.x), "l"(w1.y));
        asm("fma.rn.f32x2 %0, %1, %2, %3;" : "=l"(t1) : "l"(az23), "l"(w1.x), "l"(w1.y));
        asm("fma.rn.f32x2 %0, %1, %2, %0;" : "+l"(t0) : "l"(ay01), "l"(w0.y));
        asm("fma.rn.f32x2 %0, %1, %2, %0;" : "+l"(t1) : "l"(ay23), "l"(w0.y));
        asm("fma.rn.f32x2 %0, %1, %2, %0;" : "+l"(t0) : "l"(ax01), "l"(w0.x));
        asm("fma.rn.f32x2 %0, %1, %2, %0;" : "+l"(t1) : "l"(ax23), "l"(w0.x));
        m0 = fminf(m0, __uint_as_float((unsigned int)t0));
        m1 = fminf(m1, __uint_as_float((unsigned int)(t0 >> 32)));
        m2 = fminf(m2, __uint_as_float((unsigned int)t1));
        m3 = fminf(m3, __uint_as_float((unsigned int)(t1 >> 32)));
    }

    // add |p|^2 back; clamp tiny negative rounding so uint ordering is valid
    m0 = fmaxf(m0 + p2_0, 0.0f);
    m1 = fmaxf(m1 + p2_1, 0.0f);
    m2 = fmaxf(m2 + p2_2, 0.0f);
    m3 = fmaxf(m3 + p2_3, 0.0f);

    unsigned int* dst = &g_min[dir][bb * NPTS + qi];
    atomicMin(dst + 0, __float_as_uint(m0));
    atomicMin(dst + 1, __float_as_uint(m1));
    atomicMin(dst + 2, __float_as_uint(m2));
    atomicMin(dst + 3, __float_as_uint(m3));
}

__global__ void cd_reduce_kernel(float* __restrict__ out) {
    // single block, 1024 threads: sum both min arrays, scale, write scalar
    __shared__ float warp_sums[32];
    const int tid = threadIdx.x;
    float s = 0.0f;
    for (int i = tid; i < BATCH * NPTS; i += 1024) {
        s += __uint_as_float(g_min[0][i]);
        s += __uint_as_float(g_min[1][i]);
    }
    #pragma unroll
    for (int off = 16; off > 0; off >>= 1)
        s += __shfl_down_sync(0xFFFFFFFFu, s, off);
    if ((tid & 31) == 0) warp_sums[tid >> 5] = s;
    __syncthreads();
    if (tid < 32) {
        float v = (tid < (1024 / 32)) ? warp_sums[tid] : 0.0f;
        #pragma unroll
        for (int off = 16; off > 0; off >>= 1)
            v += __shfl_down_sync(0xFFFFFFFFu, v, off);
        if (tid == 0)
            out[0] = v / (float)(BATCH * NPTS);  // mean over N == mean over M
    }
}

extern "C" void kernel_launch(void* const* d_in, const int* in_sizes, int n_in,
                              void* d_out, int out_size) {
    const float* pred = (const float*)d_in[0];
    const float* gt   = (const float*)d_in[1];
    float* out        = (float*)d_out;

    cd_init_kernel<<<(2 * BATCH * NPTS + 1023) / 1024, 1024>>>();

    dim3 grid(ITILES * JSPLIT, 2, BATCH);   // 128 x 2 x 4 = 1024 blocks
    cd_main_kernel<<<grid, THREADS>>>(pred, gt);

    cd_reduce_kernel<<<1, 1024>>>(out);
}